// round 15
// baseline (speedup 1.0000x reference)
#include <cuda_runtime.h>
#include <cuda_fp16.h>
#include <math_constants.h>
#include <cstdint>

#define BB 2
#define NN 2048
#define FF 512
#define DD 512
#define EE 1536   // 3*DD
#define WW 128

// scratch: fp16 "hi" and "combined" (h + 64*lo) arrays
__device__ __half g_qh[BB * NN * EE];
__device__ __half g_qc[BB * NN * EE];
__device__ __half g_xh[BB * NN * FF];
__device__ __half g_xc[BB * NN * FF];
__device__ __half g_wh[EE * FF];
__device__ __half g_wc[EE * FF];

#define SPLIT_S 64.0f
#define INV_S   0.015625f

__device__ __forceinline__ uint32_t smem_u32(const void* p) {
    uint32_t a;
    asm("{ .reg .u64 t; cvta.to.shared.u64 t, %1; cvt.u32.u64 %0, t; }"
        : "=r"(a) : "l"(p));
    return a;
}

__device__ __forceinline__ void cp16(uint32_t dst, const void* src, bool valid) {
    int sz = valid ? 16 : 0;
    asm volatile("cp.async.cg.shared.global [%0], [%1], 16, %2;"
                 :: "r"(dst), "l"(src), "r"(sz) : "memory");
}

#define LDMX4(r0, r1, r2, r3, addr) \
    asm volatile("ldmatrix.sync.aligned.m8n8.x4.shared.b16 {%0, %1, %2, %3}, [%4];" \
                 : "=r"(r0), "=r"(r1), "=r"(r2), "=r"(r3) : "r"(addr))

#define LDMX2(r0, r1, addr) \
    asm volatile("ldmatrix.sync.aligned.m8n8.x2.shared.b16 {%0, %1}, [%2];" \
                 : "=r"(r0), "=r"(r1) : "r"(addr))

#define LDMX4T(r0, r1, r2, r3, addr) \
    asm volatile("ldmatrix.sync.aligned.m8n8.x4.trans.shared.b16 {%0, %1, %2, %3}, [%4];" \
                 : "=r"(r0), "=r"(r1), "=r"(r2), "=r"(r3) : "r"(addr))

#define MMA16816(acc, a, b0, b1) \
    asm volatile("mma.sync.aligned.m16n8k16.row.col.f32.f16.f16.f32 " \
                 "{%0, %1, %2, %3}, {%4, %5, %6, %7}, {%8, %9}, {%0, %1, %2, %3};" \
                 : "+f"((acc)[0]), "+f"((acc)[1]), "+f"((acc)[2]), "+f"((acc)[3]) \
                 : "r"((a)[0]), "r"((a)[1]), "r"((a)[2]), "r"((a)[3]), \
                   "r"(b0), "r"(b1))

// ---------------------------------------------------------------------------
// Conversion: fp32 -> (fp16 h, fp16 c = h + 64*(x - h)), ILP 2
// ---------------------------------------------------------------------------
__device__ __forceinline__ void split4(const float* __restrict__ src, int i,
                                       __half* __restrict__ hp_,
                                       __half* __restrict__ cp_) {
    float4 v = ((const float4*)src)[i];
    float f[4] = {v.x, v.y, v.z, v.w};
    __half h[4], c[4];
#pragma unroll
    for (int j = 0; j < 4; ++j) {
        h[j] = __float2half_rn(f[j]);
        float hl = __half2float(h[j]);
        c[j] = __float2half_rn(fmaf(SPLIT_S, f[j] - hl, hl));
    }
    __half2* hp = (__half2*)hp_;
    __half2* cp = (__half2*)cp_;
    hp[2 * i]     = __halves2half2(h[0], h[1]);
    hp[2 * i + 1] = __halves2half2(h[2], h[3]);
    cp[2 * i]     = __halves2half2(c[0], c[1]);
    cp[2 * i + 1] = __halves2half2(c[2], c[3]);
}

#define NX4 (BB * NN * FF / 4)
#define NW4 (EE * FF / 4)

__global__ void conv_all_kernel(const float* __restrict__ x,
                                const float* __restrict__ wl) {
    int base = (blockIdx.x * blockDim.x + threadIdx.x) * 2;
#pragma unroll
    for (int u = 0; u < 2; ++u) {
        int i = base + u;
        if (i < NX4) split4(x, i, g_xh, g_xc);
        else if (i < NX4 + NW4) split4(wl, i - NX4, g_wh, g_wc);
    }
}

// ---------------------------------------------------------------------------
// Kernel 1: QKV GEMM, fp16 Karatsuba 2-pass (unchanged from R14).
// ---------------------------------------------------------------------------
#define BK 64
#define QSTG 32768
#define SM_A(buf) ((buf) * QSTG + 0)
#define SM_B(buf) ((buf) * QSTG + 16384)
#define SMEM_QKV (3 * QSTG)            // 98304

__device__ __forceinline__ uint32_t swz128(int row, int ch) {
    return (uint32_t)(row * 128 + ((ch ^ (row & 7)) << 4));
}

extern __shared__ char dynsm[];

__global__ __launch_bounds__(256, 2)
void qkv_mma_kernel() {
    const int tid = threadIdx.x;
    const int lane = tid & 31;
    const int wid = tid >> 5;
    const int wr = wid & 3;
    const int wc = wid >> 2;
    const int bn = blockIdx.x * 128;
    const int bm = blockIdx.y * 128;

    const uint32_t sm = smem_u32(dynsm);

    float acc[2][8][4];
#pragma unroll
    for (int mi = 0; mi < 2; ++mi)
#pragma unroll
        for (int ni = 0; ni < 8; ++ni)
#pragma unroll
            for (int q = 0; q < 4; ++q) acc[mi][ni][q] = 0.f;

    auto issue_loads = [&](int t, int buf) {
        int pass = t >> 3;
        int k0 = (t & 7) * BK;
        const __half* A = (pass ? g_xc : g_xh) + (size_t)bm * FF + k0;
        const __half* B = (pass ? g_wc : g_wh) + (size_t)bn * FF + k0;
#pragma unroll
        for (int j = 0; j < 8; ++j) {
            int id = tid + j * 256;
            int arr = id >> 10;
            int cid = id & 1023;
            int row = cid >> 3;
            int c   = cid & 7;
            uint32_t doff = swz128(row, c);
            if (arr == 0) cp16(sm + SM_A(buf) + doff, A + row * FF + c * 8, true);
            else          cp16(sm + SM_B(buf) + doff, B + row * FF + c * 8, true);
        }
        asm volatile("cp.async.commit_group;" ::: "memory");
    };

    issue_loads(0, 0);
    issue_loads(1, 1);

    const int a_row = wr * 32 + (lane & 15);
    const int a_ch  = (lane >> 4);
    const int b_row = wc * 64 + ((lane >> 4) << 3) + (lane & 7);
    const int b_ch  = ((lane >> 3) & 1);

    for (int t = 0; t < 16; ++t) {
        const int buf = t % 3;
        if (t < 14) {
            asm volatile("cp.async.wait_group 1;" ::: "memory");
        } else {
            asm volatile("cp.async.wait_group 0;" ::: "memory");
        }
        __syncthreads();
        if (t + 2 < 16) issue_loads(t + 2, (t + 2) % 3);

#pragma unroll
        for (int kk = 0; kk < 4; ++kk) {
            uint32_t af[2][4];
#pragma unroll
            for (int mi = 0; mi < 2; ++mi) {
                int row = a_row + mi * 16;
                LDMX4(af[mi][0], af[mi][1], af[mi][2], af[mi][3],
                      sm + SM_A(buf) + swz128(row, a_ch + kk * 2));
            }
#pragma unroll
            for (int np = 0; np < 4; ++np) {
                int row = b_row + np * 16;
                uint32_t h0, h1, h2, h3;
                LDMX4(h0, h1, h2, h3, sm + SM_B(buf) + swz128(row, b_ch + kk * 2));
#pragma unroll
                for (int mi = 0; mi < 2; ++mi) {
                    MMA16816(acc[mi][2 * np],     af[mi], h0, h1);
                    MMA16816(acc[mi][2 * np + 1], af[mi], h2, h3);
                }
            }
        }
        if (t == 7) {
#pragma unroll
            for (int mi = 0; mi < 2; ++mi)
#pragma unroll
                for (int ni = 0; ni < 8; ++ni)
#pragma unroll
                    for (int q = 0; q < 4; ++q) acc[mi][ni][q] *= 63.0f;
        }
    }
    __syncthreads();

    __half* const sOutH = (__half*)dynsm;
    __half* const sOutC = (__half*)(dynsm + 32768);

    const int em = wr * 32 + (lane >> 2);
    const int en = wc * 64 + (lane & 3) * 2;
#pragma unroll
    for (int mi = 0; mi < 2; ++mi) {
#pragma unroll
        for (int ni = 0; ni < 8; ++ni) {
#pragma unroll
            for (int half_ = 0; half_ < 2; ++half_) {
                int row = em + mi * 16 + half_ * 8;
                int col = en + ni * 8;
                float v0 = acc[mi][ni][2 * half_] * INV_S;
                float v1 = acc[mi][ni][2 * half_ + 1] * INV_S;
                __half h0 = __float2half_rn(v0);
                __half h1 = __float2half_rn(v1);
                float f0 = __half2float(h0), f1 = __half2float(h1);
                __half c0 = __float2half_rn(fmaf(SPLIT_S, v0 - f0, f0));
                __half c1 = __float2half_rn(fmaf(SPLIT_S, v1 - f1, f1));
                *(__half2*)&sOutH[row * 128 + col] = __halves2half2(h0, h1);
                *(__half2*)&sOutC[row * 128 + col] = __halves2half2(c0, c1);
            }
        }
    }
    __syncthreads();

#pragma unroll
    for (int j = 0; j < 8; ++j) {
        int id = tid + j * 256;
        int row = id >> 4;
        int c16 = id & 15;
        uint4 v = *(uint4*)&sOutH[row * 128 + c16 * 8];
        *(uint4*)&g_qh[(size_t)(bm + row) * EE + bn + c16 * 8] = v;
    }
#pragma unroll
    for (int j = 0; j < 8; ++j) {
        int id = tid + j * 256;
        int row = id >> 4;
        int c16 = id & 15;
        uint4 v = *(uint4*)&sOutC[row * 128 + c16 * 8];
        *(uint4*)&g_qc[(size_t)(bm + row) * EE + bn + c16 * 8] = v;
    }
}

// ---------------------------------------------------------------------------
// Kernel 2: sliding-window attention, fp16 Karatsuba, 512 threads / 16 warps.
// Phase A: 2M x 8N (warp n-tile 24 = x4 + x2 ldmatrix).
// Phase B: 2M x 8N (warp 16x64), dual accumulators.
// ---------------------------------------------------------------------------
#define SM_QHb(buf)  ((buf) * 64512 + 0)
#define SM_QCb(buf)  ((buf) * 64512 + 4608)
#define SM_KHb(buf)  ((buf) * 64512 + 9216)
#define SM_KCb(buf)  ((buf) * 64512 + 36864)
#define SM_VHb(buf)  ((buf) * 66560 + 0)
#define SM_VCb(buf)  ((buf) * 66560 + 33280)
#define SM_S        133120
#define SM_PH       158208
#define SM_PC       171008
#define SMEM_ATTN   183808
#define QK_STR 72
#define V_STR  520
#define P_STR  200
#define S_STR  196

__global__ __launch_bounds__(512, 1)
void attn_tc_kernel(float* __restrict__ out) {
    const int tid = threadIdx.x;
    const int lane = tid & 31;
    const int wid = tid >> 5;          // 0..15
    const int wr = wid & 1;            // M group (16 rows)
    const int wc = wid >> 1;           // N group 0..7
    const int b  = blockIdx.y;
    const int q0 = blockIdx.x * 32;
    const int bbase = b * NN;

    const uint32_t sm = smem_u32(dynsm);
    float* const sS = (float*)(dynsm + SM_S);
    __half* const sPh = (__half*)(dynsm + SM_PH);
    __half* const sPc = (__half*)(dynsm + SM_PC);

    auto issueA = [&](int c, int buf) {
        int k0 = c * 64;
#pragma unroll
        for (int j = 0; j < 3; ++j) {
            int id = tid + j * 512;          // 0..1535
            int row = id >> 3, cc = id & 7;
            int n = q0 - 127 + row;
            bool valid = (row < 160) && (n >= 0) && (n < NN);
            size_t gidx = ((size_t)(bbase + (valid ? n : 0))) * EE + DD + k0 + cc * 8;
            uint32_t doff = (uint32_t)(row * QK_STR + cc * 8) * 2;
            cp16(sm + SM_KHb(buf) + doff, g_qh + gidx, valid);
            cp16(sm + SM_KCb(buf) + doff, g_qc + gidx, valid);
        }
        if (tid < 256) {
            int row = tid >> 3, cc = tid & 7;
            size_t gidx = ((size_t)(bbase + q0 + row)) * EE + k0 + cc * 8;
            uint32_t doff = (uint32_t)(row * QK_STR + cc * 8) * 2;
            cp16(sm + SM_QHb(buf) + doff, g_qh + gidx, true);
            cp16(sm + SM_QCb(buf) + doff, g_qc + gidx, true);
        }
        asm volatile("cp.async.commit_group;" ::: "memory");
    };

    auto issueV = [&](int c, int buf) {
        int r0 = c * 32;
#pragma unroll
        for (int j = 0; j < 4; ++j) {
            int id = tid + j * 512;          // 0..2047
            int row = id >> 6, cc = id & 63;
            int n = q0 - 127 + r0 + row;
            bool valid = (n >= 0) && (n < NN);
            size_t gidx = ((size_t)(bbase + (valid ? n : 0))) * EE + 2 * DD + cc * 8;
            uint32_t doff = (uint32_t)(row * V_STR + cc * 8) * 2;
            cp16(sm + SM_VHb(buf) + doff, g_qh + gidx, valid);
            cp16(sm + SM_VCb(buf) + doff, g_qc + gidx, valid);
        }
        asm volatile("cp.async.commit_group;" ::: "memory");
    };

    // ---------------- Phase A: S = (63*Qh.Kh^T + Qc.Kc^T)/64 ----------------
    float a1[3][4], a2[3][4];
#pragma unroll
    for (int ni = 0; ni < 3; ++ni)
#pragma unroll
        for (int q = 0; q < 4; ++q) { a1[ni][q] = 0.f; a2[ni][q] = 0.f; }

    const int a_row = wr * 16 + (lane & 15);
    const int a_kc  = (lane >> 4) * 8;
    const int b16_row = wc * 24 + ((lane >> 4) << 3) + (lane & 7);   // x4 (n16)
    const int b8_row  = wc * 24 + 16 + (lane & 7);                   // x2 (n8)
    const int bkc     = ((lane >> 3) & 1) * 8;

    issueA(0, 0);
    for (int c = 0; c < 8; ++c) {
        const int buf = c & 1;
        if (c < 7) {
            issueA(c + 1, buf ^ 1);
            asm volatile("cp.async.wait_group 1;" ::: "memory");
        } else {
            asm volatile("cp.async.wait_group 0;" ::: "memory");
        }
        __syncthreads();

#pragma unroll
        for (int ks = 0; ks < 4; ++ks) {
            uint32_t ah[4], ac[4];
            LDMX4(ah[0], ah[1], ah[2], ah[3],
                  sm + SM_QHb(buf) + (uint32_t)(a_row * QK_STR + a_kc + ks * 16) * 2);
            LDMX4(ac[0], ac[1], ac[2], ac[3],
                  sm + SM_QCb(buf) + (uint32_t)(a_row * QK_STR + a_kc + ks * 16) * 2);
            uint32_t off16 = (uint32_t)(b16_row * QK_STR + bkc + ks * 16) * 2;
            uint32_t off8  = (uint32_t)(b8_row * QK_STR + bkc + ks * 16) * 2;
            uint32_t kh0, kh1, kh2, kh3, kh4, kh5;
            uint32_t kc0, kc1, kc2, kc3, kc4, kc5;
            LDMX4(kh0, kh1, kh2, kh3, sm + SM_KHb(buf) + off16);
            LDMX2(kh4, kh5, sm + SM_KHb(buf) + off8);
            LDMX4(kc0, kc1, kc2, kc3, sm + SM_KCb(buf) + off16);
            LDMX2(kc4, kc5, sm + SM_KCb(buf) + off8);
            MMA16816(a1[0], ah, kh0, kh1);
            MMA16816(a1[1], ah, kh2, kh3);
            MMA16816(a1[2], ah, kh4, kh5);
            MMA16816(a2[0], ac, kc0, kc1);
            MMA16816(a2[1], ac, kc2, kc3);
            MMA16816(a2[2], ac, kc4, kc5);
        }
        __syncthreads();
    }

    // combined S = (63*M1 + M2)/64; warp region: rows wr*16+, cols wc*24+
#pragma unroll
    for (int ni = 0; ni < 3; ++ni) {
        int row = wr * 16 + (lane >> 2);
        int col = wc * 24 + ni * 8 + (lane & 3) * 2;
        sS[row * S_STR + col]           = fmaf(63.f, a1[ni][0], a2[ni][0]) * INV_S;
        sS[row * S_STR + col + 1]       = fmaf(63.f, a1[ni][1], a2[ni][1]) * INV_S;
        sS[(row + 8) * S_STR + col]     = fmaf(63.f, a1[ni][2], a2[ni][2]) * INV_S;
        sS[(row + 8) * S_STR + col + 1] = fmaf(63.f, a1[ni][3], a2[ni][3]) * INV_S;
    }

    issueV(0, 0);
    issueV(1, 1);
    __syncthreads();

    // ---------------- softmax: 16 warps x 2 rows ----------------
#pragma unroll
    for (int ii = 0; ii < 2; ++ii) {
        int i = wid * 2 + ii;
        float vals[4];
        float m = -CUDART_INF_F;
#pragma unroll
        for (int t = 0; t < 4; ++t) {
            vals[t] = sS[i * S_STR + i + lane + 32 * t];
            m = fmaxf(m, vals[t]);
        }
#pragma unroll
        for (int o = 16; o > 0; o >>= 1)
            m = fmaxf(m, __shfl_xor_sync(0xffffffffu, m, o));
        float s = 0.f;
#pragma unroll
        for (int t = 0; t < 4; ++t) s += __expf(vals[t] - m);
#pragma unroll
        for (int o = 16; o > 0; o >>= 1)
            s += __shfl_xor_sync(0xffffffffu, s, o);
        float inv = 1.f / s;
#pragma unroll
        for (int t = 0; t < 6; ++t) {
            int r = lane + 32 * t;
            int w = r - i;
            float val = (w >= 0 && w < WW) ? __expf(sS[i * S_STR + r] - m) * inv : 0.f;
            __half h = __float2half_rn(val);
            float hf = __half2float(h);
            __half pc = __float2half_rn(fmaf(SPLIT_S, val - hf, hf));
            sPh[i * P_STR + r] = h;
            sPc[i * P_STR + r] = pc;
        }
    }
    __syncthreads();

    // ---------------- Phase B: out = (63*Ph.Vh + Pc.Vc)/64 ----------------
    float o1[8][4], o2[8][4];
#pragma unroll
    for (int ni = 0; ni < 8; ++ni)
#pragma unroll
        for (int q = 0; q < 4; ++q) { o1[ni][q] = 0.f; o2[ni][q] = 0.f; }

    const int pa_row = wr * 16 + (lane & 15);
    const int v_row  = (lane & 15);
    const int v_col0 = wc * 64 + ((lane >> 4) << 3);

    for (int c = 0; c < 6; ++c) {
        if (c < 5) asm volatile("cp.async.wait_group 1;" ::: "memory");
        else       asm volatile("cp.async.wait_group 0;" ::: "memory");
        __syncthreads();
        const int buf = c & 1;

#pragma unroll
        for (int ks = 0; ks < 2; ++ks) {
            int kg = c * 32 + ks * 16;
            uint32_t ph[4], pc[4];
            LDMX4(ph[0], ph[1], ph[2], ph[3],
                  sm + SM_PH + (uint32_t)(pa_row * P_STR + kg + (lane >> 4) * 8) * 2);
            LDMX4(pc[0], pc[1], pc[2], pc[3],
                  sm + SM_PC + (uint32_t)(pa_row * P_STR + kg + (lane >> 4) * 8) * 2);
#pragma unroll
            for (int nt = 0; nt < 4; ++nt) {
                uint32_t off = (uint32_t)((ks * 16 + v_row) * V_STR + v_col0 + nt * 16) * 2;
                uint32_t h0, h1, h2, h3, c0, c1, c2, c3;
                LDMX4T(h0, h1, h2, h3, sm + SM_VHb(buf) + off);
                LDMX4T(c0, c1, c2, c3, sm + SM_VCb(buf) + off);
                MMA16816(o1[2 * nt],     ph, h0, h1);
                MMA16816(o1[2 * nt + 1], ph, h2, h3);
                MMA16816(o2[2 * nt],     pc, c0, c1);
                MMA16816(o2[2 * nt + 1], pc, c2, c3);
            }
        }
        __syncthreads();
        if (c + 2 < 6) issueV(c + 2, buf);
    }

    const int orow = q0 + wr * 16 + (lane >> 2);
    const int ocol = wc * 64 + (lane & 3) * 2;
#pragma unroll
    for (int ni = 0; ni < 8; ++ni) {
        int col = ocol + ni * 8;
        *(float2*)&out[((size_t)(bbase + orow)) * DD + col] =
            make_float2(fmaf(63.f, o1[ni][0], o2[ni][0]) * INV_S,
                        fmaf(63.f, o1[ni][1], o2[ni][1]) * INV_S);
        *(float2*)&out[((size_t)(bbase + orow + 8)) * DD + col] =
            make_float2(fmaf(63.f, o1[ni][2], o2[ni][2]) * INV_S,
                        fmaf(63.f, o1[ni][3], o2[ni][3]) * INV_S);
    }
}

extern "C" void kernel_launch(void* const* d_in, const int* in_sizes, int n_in,
                              void* d_out, int out_size) {
    const float* x  = (const float*)d_in[0];
    const float* wl = (const float*)d_in[1];
    float* out = (float*)d_out;

    cudaFuncSetAttribute(qkv_mma_kernel,
                         cudaFuncAttributeMaxDynamicSharedMemorySize, SMEM_QKV);
    cudaFuncSetAttribute(attn_tc_kernel,
                         cudaFuncAttributeMaxDynamicSharedMemorySize, SMEM_ATTN);

    const int ntot = (NX4 + NW4) / 2;
    conv_all_kernel<<<(ntot + 255) / 256, 256>>>(x, wl);

    dim3 g1(EE / 128, (BB * NN) / 128);   // 12 x 32
    qkv_mma_kernel<<<g1, 256, SMEM_QKV>>>();

    dim3 g2(NN / 32, BB);                 // 64 x 2
    attn_tc_kernel<<<g2, 512, SMEM_ATTN>>>(out);
}

// round 16
// speedup vs baseline: 1.1461x; 1.1461x over previous
#include <cuda_runtime.h>
#include <cuda_fp16.h>
#include <math_constants.h>
#include <cstdint>

#define BB 2
#define NN 2048
#define FF 512
#define DD 512
#define EE 1536   // 3*DD
#define WW 128

// scratch: fp16 "hi" and "combined" (h + 64*lo) arrays
__device__ __half g_qh[BB * NN * EE];
__device__ __half g_qc[BB * NN * EE];
__device__ __half g_xh[BB * NN * FF];
__device__ __half g_xc[BB * NN * FF];
__device__ __half g_wh[EE * FF];
__device__ __half g_wc[EE * FF];

#define SPLIT_S 64.0f
#define INV_S   0.015625f

__device__ __forceinline__ uint32_t smem_u32(const void* p) {
    uint32_t a;
    asm("{ .reg .u64 t; cvta.to.shared.u64 t, %1; cvt.u32.u64 %0, t; }"
        : "=r"(a) : "l"(p));
    return a;
}

__device__ __forceinline__ void cp16(uint32_t dst, const void* src, bool valid) {
    int sz = valid ? 16 : 0;
    asm volatile("cp.async.cg.shared.global [%0], [%1], 16, %2;"
                 :: "r"(dst), "l"(src), "r"(sz) : "memory");
}

#define LDMX4(r0, r1, r2, r3, addr) \
    asm volatile("ldmatrix.sync.aligned.m8n8.x4.shared.b16 {%0, %1, %2, %3}, [%4];" \
                 : "=r"(r0), "=r"(r1), "=r"(r2), "=r"(r3) : "r"(addr))

#define LDMX4T(r0, r1, r2, r3, addr) \
    asm volatile("ldmatrix.sync.aligned.m8n8.x4.trans.shared.b16 {%0, %1, %2, %3}, [%4];" \
                 : "=r"(r0), "=r"(r1), "=r"(r2), "=r"(r3) : "r"(addr))

#define MMA16816(acc, a, b0, b1) \
    asm volatile("mma.sync.aligned.m16n8k16.row.col.f32.f16.f16.f32 " \
                 "{%0, %1, %2, %3}, {%4, %5, %6, %7}, {%8, %9}, {%0, %1, %2, %3};" \
                 : "+f"((acc)[0]), "+f"((acc)[1]), "+f"((acc)[2]), "+f"((acc)[3]) \
                 : "r"((a)[0]), "r"((a)[1]), "r"((a)[2]), "r"((a)[3]), \
                   "r"(b0), "r"(b1))

// ---------------------------------------------------------------------------
// Conversion: fp32 -> (fp16 h, fp16 c = h + 64*(x - h))  [R14 form, ILP 1]
// ---------------------------------------------------------------------------
__device__ __forceinline__ void split4(const float* __restrict__ src, int i,
                                       __half* __restrict__ hp_,
                                       __half* __restrict__ cp_) {
    float4 v = ((const float4*)src)[i];
    float f[4] = {v.x, v.y, v.z, v.w};
    __half h[4], c[4];
#pragma unroll
    for (int j = 0; j < 4; ++j) {
        h[j] = __float2half_rn(f[j]);
        float hl = __half2float(h[j]);
        c[j] = __float2half_rn(fmaf(SPLIT_S, f[j] - hl, hl));
    }
    __half2* hp = (__half2*)hp_;
    __half2* cp = (__half2*)cp_;
    hp[2 * i]     = __halves2half2(h[0], h[1]);
    hp[2 * i + 1] = __halves2half2(h[2], h[3]);
    cp[2 * i]     = __halves2half2(c[0], c[1]);
    cp[2 * i + 1] = __halves2half2(c[2], c[3]);
}

#define NX4 (BB * NN * FF / 4)
#define NW4 (EE * FF / 4)

__global__ void conv_all_kernel(const float* __restrict__ x,
                                const float* __restrict__ wl) {
    int i = blockIdx.x * blockDim.x + threadIdx.x;
    if (i < NX4) split4(x, i, g_xh, g_xc);
    else if (i < NX4 + NW4) split4(wl, i - NX4, g_wh, g_wc);
}

// ---------------------------------------------------------------------------
// Kernel 1: QKV GEMM, fp16 Karatsuba 2-pass (R14).  Epilogue skips g_qc
// stores for the V third (blockIdx.x >= 8) — attn Phase B no longer reads it.
// ---------------------------------------------------------------------------
#define BK 64
#define QSTG 32768
#define SM_A(buf) ((buf) * QSTG + 0)
#define SM_B(buf) ((buf) * QSTG + 16384)
#define SMEM_QKV (3 * QSTG)            // 98304

__device__ __forceinline__ uint32_t swz128(int row, int ch) {
    return (uint32_t)(row * 128 + ((ch ^ (row & 7)) << 4));
}

extern __shared__ char dynsm[];

__global__ __launch_bounds__(256, 2)
void qkv_mma_kernel() {
    const int tid = threadIdx.x;
    const int lane = tid & 31;
    const int wid = tid >> 5;
    const int wr = wid & 3;
    const int wc = wid >> 2;
    const int bn = blockIdx.x * 128;
    const int bm = blockIdx.y * 128;

    const uint32_t sm = smem_u32(dynsm);

    float acc[2][8][4];
#pragma unroll
    for (int mi = 0; mi < 2; ++mi)
#pragma unroll
        for (int ni = 0; ni < 8; ++ni)
#pragma unroll
            for (int q = 0; q < 4; ++q) acc[mi][ni][q] = 0.f;

    auto issue_loads = [&](int t, int buf) {
        int pass = t >> 3;
        int k0 = (t & 7) * BK;
        const __half* A = (pass ? g_xc : g_xh) + (size_t)bm * FF + k0;
        const __half* B = (pass ? g_wc : g_wh) + (size_t)bn * FF + k0;
#pragma unroll
        for (int j = 0; j < 8; ++j) {
            int id = tid + j * 256;
            int arr = id >> 10;
            int cid = id & 1023;
            int row = cid >> 3;
            int c   = cid & 7;
            uint32_t doff = swz128(row, c);
            if (arr == 0) cp16(sm + SM_A(buf) + doff, A + row * FF + c * 8, true);
            else          cp16(sm + SM_B(buf) + doff, B + row * FF + c * 8, true);
        }
        asm volatile("cp.async.commit_group;" ::: "memory");
    };

    issue_loads(0, 0);
    issue_loads(1, 1);

    const int a_row = wr * 32 + (lane & 15);
    const int a_ch  = (lane >> 4);
    const int b_row = wc * 64 + ((lane >> 4) << 3) + (lane & 7);
    const int b_ch  = ((lane >> 3) & 1);

    for (int t = 0; t < 16; ++t) {
        const int buf = t % 3;
        if (t < 14) {
            asm volatile("cp.async.wait_group 1;" ::: "memory");
        } else {
            asm volatile("cp.async.wait_group 0;" ::: "memory");
        }
        __syncthreads();
        if (t + 2 < 16) issue_loads(t + 2, (t + 2) % 3);

#pragma unroll
        for (int kk = 0; kk < 4; ++kk) {
            uint32_t af[2][4];
#pragma unroll
            for (int mi = 0; mi < 2; ++mi) {
                int row = a_row + mi * 16;
                LDMX4(af[mi][0], af[mi][1], af[mi][2], af[mi][3],
                      sm + SM_A(buf) + swz128(row, a_ch + kk * 2));
            }
#pragma unroll
            for (int np = 0; np < 4; ++np) {
                int row = b_row + np * 16;
                uint32_t h0, h1, h2, h3;
                LDMX4(h0, h1, h2, h3, sm + SM_B(buf) + swz128(row, b_ch + kk * 2));
#pragma unroll
                for (int mi = 0; mi < 2; ++mi) {
                    MMA16816(acc[mi][2 * np],     af[mi], h0, h1);
                    MMA16816(acc[mi][2 * np + 1], af[mi], h2, h3);
                }
            }
        }
        if (t == 7) {
#pragma unroll
            for (int mi = 0; mi < 2; ++mi)
#pragma unroll
                for (int ni = 0; ni < 8; ++ni)
#pragma unroll
                    for (int q = 0; q < 4; ++q) acc[mi][ni][q] *= 63.0f;
        }
    }
    __syncthreads();

    __half* const sOutH = (__half*)dynsm;
    __half* const sOutC = (__half*)(dynsm + 32768);
    const bool needC = (blockIdx.x < 8);   // q,k thirds only

    const int em = wr * 32 + (lane >> 2);
    const int en = wc * 64 + (lane & 3) * 2;
#pragma unroll
    for (int mi = 0; mi < 2; ++mi) {
#pragma unroll
        for (int ni = 0; ni < 8; ++ni) {
#pragma unroll
            for (int half_ = 0; half_ < 2; ++half_) {
                int row = em + mi * 16 + half_ * 8;
                int col = en + ni * 8;
                float v0 = acc[mi][ni][2 * half_] * INV_S;
                float v1 = acc[mi][ni][2 * half_ + 1] * INV_S;
                __half h0 = __float2half_rn(v0);
                __half h1 = __float2half_rn(v1);
                *(__half2*)&sOutH[row * 128 + col] = __halves2half2(h0, h1);
                if (needC) {
                    float f0 = __half2float(h0), f1 = __half2float(h1);
                    __half c0 = __float2half_rn(fmaf(SPLIT_S, v0 - f0, f0));
                    __half c1 = __float2half_rn(fmaf(SPLIT_S, v1 - f1, f1));
                    *(__half2*)&sOutC[row * 128 + col] = __halves2half2(c0, c1);
                }
            }
        }
    }
    __syncthreads();

#pragma unroll
    for (int j = 0; j < 8; ++j) {
        int id = tid + j * 256;
        int row = id >> 4;
        int c16 = id & 15;
        uint4 v = *(uint4*)&sOutH[row * 128 + c16 * 8];
        *(uint4*)&g_qh[(size_t)(bm + row) * EE + bn + c16 * 8] = v;
    }
    if (needC) {
#pragma unroll
        for (int j = 0; j < 8; ++j) {
            int id = tid + j * 256;
            int row = id >> 4;
            int c16 = id & 15;
            uint4 v = *(uint4*)&sOutC[row * 128 + c16 * 8];
            *(uint4*)&g_qc[(size_t)(bm + row) * EE + bn + c16 * 8] = v;
        }
    }
}

// ---------------------------------------------------------------------------
// Kernel 2: sliding-window attention (R14 256-thread structure).
// Phase A: dual-path Karatsuba (precision lives in the exponent).
// Phase B: single plain-fp16 P.V  (error ~2-4e-4 global, under 1e-3).
// ---------------------------------------------------------------------------
#define SM_QHb(buf)  ((buf) * 64512 + 0)
#define SM_QCb(buf)  ((buf) * 64512 + 4608)
#define SM_KHb(buf)  ((buf) * 64512 + 9216)
#define SM_KCb(buf)  ((buf) * 64512 + 36864)
#define SM_VHb(buf)  ((buf) * 33280 + 0)
#define SM_S        133120
#define SM_PH       158208
#define SMEM_ATTN   171008
#define QK_STR 72
#define V_STR  520
#define P_STR  200
#define S_STR  196

__global__ __launch_bounds__(256, 1)
void attn_tc_kernel(float* __restrict__ out) {
    const int tid = threadIdx.x;
    const int lane = tid & 31;
    const int wid = tid >> 5;
    const int wr = wid & 1;
    const int wc = wid >> 1;
    const int b  = blockIdx.y;
    const int q0 = blockIdx.x * 32;
    const int bbase = b * NN;

    const uint32_t sm = smem_u32(dynsm);
    float* const sS = (float*)(dynsm + SM_S);
    __half* const sPh = (__half*)(dynsm + SM_PH);

    auto issueA = [&](int c, int buf) {
        int k0 = c * 64;
#pragma unroll
        for (int j = 0; j < 6; ++j) {
            int id = tid + j * 256;
            int row = id >> 3, cc = id & 7;
            int n = q0 - 127 + row;
            bool valid = (row < 160) && (n >= 0) && (n < NN);
            size_t gidx = ((size_t)(bbase + (valid ? n : 0))) * EE + DD + k0 + cc * 8;
            uint32_t doff = (uint32_t)(row * QK_STR + cc * 8) * 2;
            cp16(sm + SM_KHb(buf) + doff, g_qh + gidx, valid);
            cp16(sm + SM_KCb(buf) + doff, g_qc + gidx, valid);
        }
        {
            int row = tid >> 3, cc = tid & 7;
            size_t gidx = ((size_t)(bbase + q0 + row)) * EE + k0 + cc * 8;
            uint32_t doff = (uint32_t)(row * QK_STR + cc * 8) * 2;
            cp16(sm + SM_QHb(buf) + doff, g_qh + gidx, true);
            cp16(sm + SM_QCb(buf) + doff, g_qc + gidx, true);
        }
        asm volatile("cp.async.commit_group;" ::: "memory");
    };

    auto issueV = [&](int c, int buf) {
        int r0 = c * 32;
#pragma unroll
        for (int j = 0; j < 8; ++j) {
            int id = tid + j * 256;
            int row = id >> 6, cc = id & 63;
            int n = q0 - 127 + r0 + row;
            bool valid = (n >= 0) && (n < NN);
            size_t gidx = ((size_t)(bbase + (valid ? n : 0))) * EE + 2 * DD + cc * 8;
            uint32_t doff = (uint32_t)(row * V_STR + cc * 8) * 2;
            cp16(sm + SM_VHb(buf) + doff, g_qh + gidx, valid);
        }
        asm volatile("cp.async.commit_group;" ::: "memory");
    };

    // ---------------- Phase A: S = (63*Qh.Kh^T + Qc.Kc^T)/64 ----------------
    float a1[6][4], a2[6][4];
#pragma unroll
    for (int ni = 0; ni < 6; ++ni)
#pragma unroll
        for (int q = 0; q < 4; ++q) { a1[ni][q] = 0.f; a2[ni][q] = 0.f; }

    const int a_row = wr * 16 + (lane & 15);
    const int a_kc  = (lane >> 4) * 8;
    const int bA_row = wc * 48 + ((lane >> 4) << 3) + (lane & 7);
    const int bA_kc  = ((lane >> 3) & 1) * 8;

    issueA(0, 0);
    for (int c = 0; c < 8; ++c) {
        const int buf = c & 1;
        if (c < 7) {
            issueA(c + 1, buf ^ 1);
            asm volatile("cp.async.wait_group 1;" ::: "memory");
        } else {
            asm volatile("cp.async.wait_group 0;" ::: "memory");
        }
        __syncthreads();

#pragma unroll
        for (int ks = 0; ks < 4; ++ks) {
            uint32_t ah[4], ac[4];
            LDMX4(ah[0], ah[1], ah[2], ah[3],
                  sm + SM_QHb(buf) + (uint32_t)(a_row * QK_STR + a_kc + ks * 16) * 2);
            LDMX4(ac[0], ac[1], ac[2], ac[3],
                  sm + SM_QCb(buf) + (uint32_t)(a_row * QK_STR + a_kc + ks * 16) * 2);
            uint32_t kh[6][2], kc[6][2];
#pragma unroll
            for (int np = 0; np < 3; ++np) {
                uint32_t off = (uint32_t)((bA_row + np * 16) * QK_STR + bA_kc + ks * 16) * 2;
                uint32_t r0, r1, r2, r3;
                LDMX4(r0, r1, r2, r3, sm + SM_KHb(buf) + off);
                kh[2 * np][0] = r0; kh[2 * np][1] = r1;
                kh[2 * np + 1][0] = r2; kh[2 * np + 1][1] = r3;
                LDMX4(r0, r1, r2, r3, sm + SM_KCb(buf) + off);
                kc[2 * np][0] = r0; kc[2 * np][1] = r1;
                kc[2 * np + 1][0] = r2; kc[2 * np + 1][1] = r3;
            }
#pragma unroll
            for (int ni = 0; ni < 6; ++ni) {
                MMA16816(a1[ni], ah, kh[ni][0], kh[ni][1]);
                MMA16816(a2[ni], ac, kc[ni][0], kc[ni][1]);
            }
        }
        __syncthreads();
    }

    // combined S = (63*M1 + M2)/64
#pragma unroll
    for (int ni = 0; ni < 6; ++ni) {
        int row = wr * 16 + (lane >> 2);
        int col = wc * 48 + ni * 8 + (lane & 3) * 2;
        sS[row * S_STR + col]           = fmaf(63.f, a1[ni][0], a2[ni][0]) * INV_S;
        sS[row * S_STR + col + 1]       = fmaf(63.f, a1[ni][1], a2[ni][1]) * INV_S;
        sS[(row + 8) * S_STR + col]     = fmaf(63.f, a1[ni][2], a2[ni][2]) * INV_S;
        sS[(row + 8) * S_STR + col + 1] = fmaf(63.f, a1[ni][3], a2[ni][3]) * INV_S;
    }

    issueV(0, 0);
    issueV(1, 1);
    __syncthreads();

    // ---------------- softmax over band ----------------
#pragma unroll
    for (int ii = 0; ii < 4; ++ii) {
        int i = wid * 4 + ii;
        float vals[4];
        float m = -CUDART_INF_F;
#pragma unroll
        for (int t = 0; t < 4; ++t) {
            vals[t] = sS[i * S_STR + i + lane + 32 * t];
            m = fmaxf(m, vals[t]);
        }
#pragma unroll
        for (int o = 16; o > 0; o >>= 1)
            m = fmaxf(m, __shfl_xor_sync(0xffffffffu, m, o));
        float s = 0.f;
#pragma unroll
        for (int t = 0; t < 4; ++t) s += __expf(vals[t] - m);
#pragma unroll
        for (int o = 16; o > 0; o >>= 1)
            s += __shfl_xor_sync(0xffffffffu, s, o);
        float inv = 1.f / s;
#pragma unroll
        for (int t = 0; t < 6; ++t) {
            int r = lane + 32 * t;
            int w = r - i;
            float val = (w >= 0 && w < WW) ? __expf(sS[i * S_STR + r] - m) * inv : 0.f;
            sPh[i * P_STR + r] = __float2half_rn(val);
        }
    }
    __syncthreads();

    // ---------------- Phase B: out = Ph.Vh (plain fp16) ----------------
    float o1[16][4];
#pragma unroll
    for (int ni = 0; ni < 16; ++ni)
#pragma unroll
        for (int q = 0; q < 4; ++q) o1[ni][q] = 0.f;

    const int pa_row = wr * 16 + (lane & 15);
    const int v_row  = (lane & 15);
    const int v_col0 = wc * 128 + ((lane >> 4) << 3);

    for (int c = 0; c < 6; ++c) {
        if (c < 5) asm volatile("cp.async.wait_group 1;" ::: "memory");
        else       asm volatile("cp.async.wait_group 0;" ::: "memory");
        __syncthreads();
        const int buf = c & 1;

#pragma unroll
        for (int ks = 0; ks < 2; ++ks) {
            int kg = c * 32 + ks * 16;
            uint32_t ph[4];
            LDMX4(ph[0], ph[1], ph[2], ph[3],
                  sm + SM_PH + (uint32_t)(pa_row * P_STR + kg + (lane >> 4) * 8) * 2);
#pragma unroll
            for (int nt = 0; nt < 8; ++nt) {
                uint32_t off = (uint32_t)((ks * 16 + v_row) * V_STR + v_col0 + nt * 16) * 2;
                uint32_t h0, h1, h2, h3;
                LDMX4T(h0, h1, h2, h3, sm + SM_VHb(buf) + off);
                MMA16816(o1[2 * nt],     ph, h0, h1);
                MMA16816(o1[2 * nt + 1], ph, h2, h3);
            }
        }
        __syncthreads();
        if (c + 2 < 6) issueV(c + 2, buf);
    }

    const int orow = q0 + wr * 16 + (lane >> 2);
    const int ocol = wc * 128 + (lane & 3) * 2;
#pragma unroll
    for (int ni = 0; ni < 16; ++ni) {
        int col = ocol + ni * 8;
        *(float2*)&out[((size_t)(bbase + orow)) * DD + col] =
            make_float2(o1[ni][0], o1[ni][1]);
        *(float2*)&out[((size_t)(bbase + orow + 8)) * DD + col] =
            make_float2(o1[ni][2], o1[ni][3]);
    }
}

extern "C" void kernel_launch(void* const* d_in, const int* in_sizes, int n_in,
                              void* d_out, int out_size) {
    const float* x  = (const float*)d_in[0];
    const float* wl = (const float*)d_in[1];
    float* out = (float*)d_out;

    cudaFuncSetAttribute(qkv_mma_kernel,
                         cudaFuncAttributeMaxDynamicSharedMemorySize, SMEM_QKV);
    cudaFuncSetAttribute(attn_tc_kernel,
                         cudaFuncAttributeMaxDynamicSharedMemorySize, SMEM_ATTN);

    const int ntot = NX4 + NW4;
    conv_all_kernel<<<(ntot + 255) / 256, 256>>>(x, wl);

    dim3 g1(EE / 128, (BB * NN) / 128);   // 12 x 32
    qkv_mma_kernel<<<g1, 256, SMEM_QKV>>>();

    dim3 g2(NN / 32, BB);                 // 64 x 2
    attn_tc_kernel<<<g2, 256, SMEM_ATTN>>>(out);
}